// round 14
// baseline (speedup 1.0000x reference)
#include <cuda_runtime.h>
#include <cuda_fp16.h>
#include <math.h>
#include <stdint.h>

#define D 1024
#define F 4096
#define MTOT 8192

typedef __half fp16;

// ---- scratch (static device globals: allocation-free) ----
__device__ fp16 g_x16[(size_t)MTOT * D];  // 16 MB
__device__ fp16 g_wfc[(size_t)F * D];     // 8 MB
__device__ fp16 g_h16[(size_t)MTOT * F];  // 64 MB
__device__ fp16 g_wp[(size_t)D * F];      // 8 MB
__device__ unsigned int g_max2[2];

// ===========================================================================
// helpers
// ===========================================================================
__device__ __forceinline__ uint32_t smem_u32(const void* p) {
    uint32_t a;
    asm("{ .reg .u64 t; cvta.to.shared.u64 t, %1; cvt.u32.u64 %0, t; }" : "=r"(a) : "l"(p));
    return a;
}
__device__ __forceinline__ void cp16(uint32_t s, const void* g) {
    asm volatile("cp.async.cg.shared.global [%0], [%1], 16;" :: "r"(s), "l"(g));
}
__device__ __forceinline__ void cp_commit() {
    asm volatile("cp.async.commit_group;");
}
__device__ __forceinline__ void cp_wait1() {
    asm volatile("cp.async.wait_group 1;");
}
__device__ __forceinline__ void ldsm4(uint32_t a, uint32_t& r0, uint32_t& r1,
                                      uint32_t& r2, uint32_t& r3) {
    asm volatile("ldmatrix.sync.aligned.m8n8.x4.shared.b16 {%0,%1,%2,%3}, [%4];"
                 : "=r"(r0), "=r"(r1), "=r"(r2), "=r"(r3) : "r"(a));
}
__device__ __forceinline__ void mma16816(float* c, const uint32_t* a, uint32_t b0, uint32_t b1) {
    asm volatile(
        "mma.sync.aligned.m16n8k16.row.col.f32.f16.f16.f32 "
        "{%0,%1,%2,%3}, {%4,%5,%6,%7}, {%8,%9}, {%0,%1,%2,%3};"
        : "+f"(c[0]), "+f"(c[1]), "+f"(c[2]), "+f"(c[3])
        : "r"(a[0]), "r"(a[1]), "r"(a[2]), "r"(a[3]), "r"(b0), "r"(b1));
}

// ===========================================================================
// pre-pass kernels
// ===========================================================================
__global__ void k_init_max() { g_max2[0] = 0u; g_max2[1] = 0u; }

// blockIdx.y selects tensor (0: W_fc, 1: W_proj); both are F*D floats.
__global__ void k_absmax2(const float* __restrict__ W0, const float* __restrict__ W1) {
    int sel = blockIdx.y;
    const float* W = sel ? W1 : W0;
    int n = F * D;
    float m = 0.f;
    int stride = gridDim.x * blockDim.x;
    for (int i = blockIdx.x * blockDim.x + threadIdx.x; i < n; i += stride)
        m = fmaxf(m, fabsf(W[i]));
    #pragma unroll
    for (int o = 16; o; o >>= 1) m = fmaxf(m, __shfl_xor_sync(0xffffffffu, m, o));
    __shared__ float sm[8];
    int lane = threadIdx.x & 31, w = threadIdx.x >> 5;
    if (lane == 0) sm[w] = m;
    __syncthreads();
    if (threadIdx.x == 0) {
        float mm = sm[0];
        for (int i = 1; i < 8; i++) mm = fmaxf(mm, sm[i]);
        atomicMax(&g_max2[sel], __float_as_uint(mm));
    }
}

// fakequant(W) + 2*B@A -> single fp16, row-major [out, K]
// One block covers 1024 cols of one row; float4 per thread.
__global__ void k_quant_w(const float* __restrict__ W, const float* __restrict__ A,
                          const float* __restrict__ Bm, fp16* __restrict__ Wo,
                          int K, int sel) {
    int o = blockIdx.y;
    __shared__ float Bs[16];
    if (threadIdx.x < 16) Bs[threadIdx.x] = Bm[o * 16 + threadIdx.x];
    __syncthreads();
    float mx = __uint_as_float(g_max2[sel]);
    float scale = mx * (1.0f / 127.0f);
    float inv   = 127.0f / mx;
    int k = (blockIdx.x * blockDim.x + threadIdx.x) * 4;
    float4 w4 = *(const float4*)(W + (size_t)o * K + k);
    float q0 = fminf(fmaxf(rintf(w4.x * inv), -128.f), 127.f) * scale;
    float q1 = fminf(fmaxf(rintf(w4.y * inv), -128.f), 127.f) * scale;
    float q2 = fminf(fmaxf(rintf(w4.z * inv), -128.f), 127.f) * scale;
    float q3 = fminf(fmaxf(rintf(w4.w * inv), -128.f), 127.f) * scale;
    float a0 = 0.f, a1 = 0.f, a2 = 0.f, a3 = 0.f;
    #pragma unroll
    for (int r = 0; r < 16; r++) {
        float4 av = *(const float4*)(A + (size_t)r * K + k);
        float b = Bs[r];
        a0 = fmaf(b, av.x, a0); a1 = fmaf(b, av.y, a1);
        a2 = fmaf(b, av.z, a2); a3 = fmaf(b, av.w, a3);
    }
    __half2 h01 = __floats2half2_rn(q0 + 2.0f * a0, q1 + 2.0f * a1);
    __half2 h23 = __floats2half2_rn(q2 + 2.0f * a2, q3 + 2.0f * a3);
    uint2 pk;
    pk.x = *(uint32_t*)&h01;
    pk.y = *(uint32_t*)&h23;
    *(uint2*)(Wo + (size_t)o * K + k) = pk;
}

__global__ void k_convert_x(const float4* __restrict__ x, fp16* __restrict__ xo) {
    size_t i = (size_t)blockIdx.x * blockDim.x + threadIdx.x;
    float4 v = x[i];
    __half2* p = (__half2*)(xo + i * 4);
    p[0] = __floats2half2_rn(v.x, v.y);
    p[1] = __floats2half2_rn(v.z, v.w);
}

// ===========================================================================
// GEMM: C[M,N] = A[M,K] * B[N,K]^T + bias, pure fp16, fp32 accum
// CTA tile 128x256, BK=64 (padded rows, 144B stride), 3-stage cp.async ring,
// ONE barrier per iteration, serial ldsm fragments (no reg double-buffer).
// 8 warps = 2(m) x 4(n), warp tile 64x64.
// MODE 0: epilogue bias + exact GELU -> fp16 H (row-major)
// MODE 1: epilogue bias -> fp32 out
// ===========================================================================
#define BK 64
#define RSB 144                       // 128B data + 16B pad
#define MAT_A (128 * RSB)             // 18432
#define MAT_Bm (256 * RSB)            // 36864
#define STAGE_B (MAT_A + MAT_Bm)      // 55296
#define NSTAGE 3
#define GSMEM (NSTAGE * STAGE_B)      // 165888

template <int MODE>
__global__ void __launch_bounds__(256, 1)
k_gemm(const fp16* __restrict__ Ax, const fp16* __restrict__ Bw,
       const float* __restrict__ bias, float* __restrict__ outf,
       fp16* __restrict__ outH, int K, int N) {
    extern __shared__ char smem[];
    uint32_t sb = smem_u32(smem);
    int tid = threadIdx.x, wid = tid >> 5, lane = tid & 31;
    int m0 = blockIdx.y * 128;
    int n0 = blockIdx.x * 256;
    int warp_m = (wid >> 2) * 64;
    int warp_n = (wid & 3) * 64;

    float acc[4][8][4];
    #pragma unroll
    for (int i = 0; i < 4; i++)
        #pragma unroll
        for (int j = 0; j < 8; j++)
            #pragma unroll
            for (int q = 0; q < 4; q++) acc[i][j][q] = 0.f;

    int KT = K / BK;

    uint32_t a_off[4], b_off[4];
    #pragma unroll
    for (int mi = 0; mi < 4; mi++)
        a_off[mi] = (uint32_t)((warp_m + mi * 16 + (lane & 15)) * RSB + (lane >> 4) * 16);
    #pragma unroll
    for (int g = 0; g < 4; g++)
        b_off[g] = (uint32_t)(MAT_A + (warp_n + g * 16 + (lane & 15)) * RSB + (lane >> 4) * 16);

    // cp.async mapping, BK=64 -> 128B data per row.
    // A: 128 rows x 8 chunks of 16B; thread t -> row t>>1, chunks (t&1)*4+0..3
    int a_row = tid >> 1;
    int a_c0  = (tid & 1) * 4;
    auto load_stage = [&](int slot, int kt) {
        uint32_t st = sb + slot * STAGE_B;
        int kb = kt * BK;
        const fp16* ga = Ax + (size_t)(m0 + a_row) * K + kb + a_c0 * 8;
        uint32_t sa = st + (uint32_t)(a_row * RSB + a_c0 * 16);
        #pragma unroll
        for (int i = 0; i < 4; i++)
            cp16(sa + i * 16, ga + i * 8);
        // B: 256 rows x 8 chunks; thread t -> row t, all 8 chunks
        const fp16* gb = Bw + (size_t)(n0 + tid) * K + kb;
        uint32_t sbb = st + (uint32_t)(MAT_A + tid * RSB);
        #pragma unroll
        for (int j = 0; j < 8; j++)
            cp16(sbb + j * 16, gb + j * 8);
        cp_commit();
    };

    load_stage(0, 0);
    load_stage(1, 1);

    for (int kt = 0; kt < KT; kt++) {
        cp_wait1();
        __syncthreads();
        if (kt + 2 < KT) load_stage((kt + 2) % NSTAGE, kt + 2);

        uint32_t st = sb + (kt % NSTAGE) * STAGE_B;
        #pragma unroll
        for (int s = 0; s < 4; s++) {
            uint32_t ks = s * 32;
            uint32_t af[4][4], bf[4][4];
            #pragma unroll
            for (int g = 0; g < 4; g++)
                ldsm4(st + b_off[g] + ks, bf[g][0], bf[g][1], bf[g][2], bf[g][3]);
            #pragma unroll
            for (int mi = 0; mi < 4; mi++)
                ldsm4(st + a_off[mi] + ks, af[mi][0], af[mi][1], af[mi][2], af[mi][3]);
            #pragma unroll
            for (int mi = 0; mi < 4; mi++) {
                #pragma unroll
                for (int ni = 0; ni < 8; ni++) {
                    int g = ni >> 1, sel = ni & 1;
                    mma16816(acc[mi][ni], af[mi], bf[g][sel], bf[g][sel + 2]);
                }
            }
        }
        // no end-of-loop barrier: next iteration's top barrier orders the
        // slot reuse (writes only issued after that barrier).
    }

    // ---- epilogue ----
    int gid = lane >> 2, tig = lane & 3;
    #pragma unroll
    for (int mi = 0; mi < 4; mi++) {
        int row = m0 + warp_m + mi * 16 + gid;
        #pragma unroll
        for (int ni = 0; ni < 8; ni++) {
            int col = n0 + warp_n + ni * 8 + tig * 2;
            float bcol0 = __ldg(&bias[col]), bcol1 = __ldg(&bias[col + 1]);
            #pragma unroll
            for (int half = 0; half < 2; half++) {
                int rr = row + half * 8;
                float v0 = acc[mi][ni][half * 2 + 0] + bcol0;
                float v1 = acc[mi][ni][half * 2 + 1] + bcol1;
                if (MODE == 0) {
                    v0 = 0.5f * v0 * (1.0f + erff(v0 * 0.70710678118654752f));
                    v1 = 0.5f * v1 * (1.0f + erff(v1 * 0.70710678118654752f));
                    *(__half2*)(outH + (size_t)rr * N + col) = __floats2half2_rn(v0, v1);
                } else {
                    float2 v; v.x = v0; v.y = v1;
                    *(float2*)(outf + (size_t)rr * N + col) = v;
                }
            }
        }
    }
}

// ===========================================================================
extern "C" void kernel_launch(void* const* d_in, const int* in_sizes, int n_in,
                              void* d_out, int out_size) {
    const float* x      = (const float*)d_in[0];
    const float* W_fc   = (const float*)d_in[1];
    const float* b_fc   = (const float*)d_in[2];
    const float* A_fc   = (const float*)d_in[3];
    const float* B_fc   = (const float*)d_in[4];
    const float* W_proj = (const float*)d_in[5];
    const float* b_proj = (const float*)d_in[6];
    const float* A_proj = (const float*)d_in[7];
    const float* B_proj = (const float*)d_in[8];
    float* out = (float*)d_out;

    fp16 *x16, *wfc, *h16, *wp;
    cudaGetSymbolAddress((void**)&x16, g_x16);
    cudaGetSymbolAddress((void**)&wfc, g_wfc);
    cudaGetSymbolAddress((void**)&h16, g_h16);
    cudaGetSymbolAddress((void**)&wp,  g_wp);

    cudaFuncSetAttribute(k_gemm<0>, cudaFuncAttributeMaxDynamicSharedMemorySize, GSMEM);
    cudaFuncSetAttribute(k_gemm<1>, cudaFuncAttributeMaxDynamicSharedMemorySize, GSMEM);

    k_init_max<<<1, 32>>>();
    k_absmax2<<<dim3(128, 2), 256>>>(W_fc, W_proj);

    k_quant_w<<<dim3(D / 1024, F), 256>>>(W_fc,   A_fc,   B_fc,   wfc, D, 0);
    k_quant_w<<<dim3(F / 1024, D), 256>>>(W_proj, A_proj, B_proj, wp,  F, 1);
    k_convert_x<<<(MTOT * D / 4) / 256, 256>>>((const float4*)x, x16);

    // GEMM1: [8192,1024] x [4096,1024]^T -> GELU -> fp16 H
    k_gemm<0><<<dim3(F / 256, MTOT / 128), 256, GSMEM>>>(
        x16, wfc, b_fc, nullptr, h16, D, F);
    // GEMM2: [8192,4096] x [1024,4096]^T -> fp32 out
    k_gemm<1><<<dim3(D / 256, MTOT / 128), 256, GSMEM>>>(
        h16, wp, b_proj, out, nullptr, F, D);
}

// round 15
// speedup vs baseline: 1.2058x; 1.2058x over previous
#include <cuda_runtime.h>
#include <cuda_fp16.h>
#include <math.h>
#include <stdint.h>

#define D 1024
#define F 4096
#define MTOT 8192

typedef __half fp16;

// ---- scratch (static device globals: allocation-free) ----
__device__ fp16 g_x16[(size_t)MTOT * D];  // 16 MB
__device__ fp16 g_wfc[(size_t)F * D];     // 8 MB
__device__ fp16 g_h16[(size_t)MTOT * F];  // 64 MB
__device__ fp16 g_wp[(size_t)D * F];      // 8 MB
__device__ unsigned int g_max2[2];

// ===========================================================================
// helpers
// ===========================================================================
__device__ __forceinline__ uint32_t smem_u32(const void* p) {
    uint32_t a;
    asm("{ .reg .u64 t; cvta.to.shared.u64 t, %1; cvt.u32.u64 %0, t; }" : "=r"(a) : "l"(p));
    return a;
}
__device__ __forceinline__ void cp16(uint32_t s, const void* g) {
    asm volatile("cp.async.cg.shared.global [%0], [%1], 16;" :: "r"(s), "l"(g));
}
__device__ __forceinline__ void cp_commit() {
    asm volatile("cp.async.commit_group;");
}
__device__ __forceinline__ void cp_wait3() {
    asm volatile("cp.async.wait_group 3;");
}
__device__ __forceinline__ void ldsm4(uint32_t a, uint32_t& r0, uint32_t& r1,
                                      uint32_t& r2, uint32_t& r3) {
    asm volatile("ldmatrix.sync.aligned.m8n8.x4.shared.b16 {%0,%1,%2,%3}, [%4];"
                 : "=r"(r0), "=r"(r1), "=r"(r2), "=r"(r3) : "r"(a));
}
__device__ __forceinline__ void mma16816(float* c, const uint32_t* a, uint32_t b0, uint32_t b1) {
    asm volatile(
        "mma.sync.aligned.m16n8k16.row.col.f32.f16.f16.f32 "
        "{%0,%1,%2,%3}, {%4,%5,%6,%7}, {%8,%9}, {%0,%1,%2,%3};"
        : "+f"(c[0]), "+f"(c[1]), "+f"(c[2]), "+f"(c[3])
        : "r"(a[0]), "r"(a[1]), "r"(a[2]), "r"(a[3]), "r"(b0), "r"(b1));
}

// ===========================================================================
// pre-pass kernels
// ===========================================================================
__global__ void k_init_max() { g_max2[0] = 0u; g_max2[1] = 0u; }

// blockIdx.y selects tensor (0: W_fc, 1: W_proj); both are F*D floats.
__global__ void k_absmax2(const float* __restrict__ W0, const float* __restrict__ W1) {
    int sel = blockIdx.y;
    const float* W = sel ? W1 : W0;
    int n = F * D;
    float m = 0.f;
    int stride = gridDim.x * blockDim.x;
    for (int i = blockIdx.x * blockDim.x + threadIdx.x; i < n; i += stride)
        m = fmaxf(m, fabsf(W[i]));
    #pragma unroll
    for (int o = 16; o; o >>= 1) m = fmaxf(m, __shfl_xor_sync(0xffffffffu, m, o));
    __shared__ float sm[8];
    int lane = threadIdx.x & 31, w = threadIdx.x >> 5;
    if (lane == 0) sm[w] = m;
    __syncthreads();
    if (threadIdx.x == 0) {
        float mm = sm[0];
        for (int i = 1; i < 8; i++) mm = fmaxf(mm, sm[i]);
        atomicMax(&g_max2[sel], __float_as_uint(mm));
    }
}

// fakequant(W) + 2*B@A -> single fp16, row-major [out, K]
// One block covers 1024 cols of one row; float4 per thread.
__global__ void k_quant_w(const float* __restrict__ W, const float* __restrict__ A,
                          const float* __restrict__ Bm, fp16* __restrict__ Wo,
                          int K, int sel) {
    int o = blockIdx.y;
    __shared__ float Bs[16];
    if (threadIdx.x < 16) Bs[threadIdx.x] = Bm[o * 16 + threadIdx.x];
    __syncthreads();
    float mx = __uint_as_float(g_max2[sel]);
    float scale = mx * (1.0f / 127.0f);
    float inv   = 127.0f / mx;
    int k = (blockIdx.x * blockDim.x + threadIdx.x) * 4;
    float4 w4 = *(const float4*)(W + (size_t)o * K + k);
    float q0 = fminf(fmaxf(rintf(w4.x * inv), -128.f), 127.f) * scale;
    float q1 = fminf(fmaxf(rintf(w4.y * inv), -128.f), 127.f) * scale;
    float q2 = fminf(fmaxf(rintf(w4.z * inv), -128.f), 127.f) * scale;
    float q3 = fminf(fmaxf(rintf(w4.w * inv), -128.f), 127.f) * scale;
    float a0 = 0.f, a1 = 0.f, a2 = 0.f, a3 = 0.f;
    #pragma unroll
    for (int r = 0; r < 16; r++) {
        float4 av = *(const float4*)(A + (size_t)r * K + k);
        float b = Bs[r];
        a0 = fmaf(b, av.x, a0); a1 = fmaf(b, av.y, a1);
        a2 = fmaf(b, av.z, a2); a3 = fmaf(b, av.w, a3);
    }
    __half2 h01 = __floats2half2_rn(q0 + 2.0f * a0, q1 + 2.0f * a1);
    __half2 h23 = __floats2half2_rn(q2 + 2.0f * a2, q3 + 2.0f * a3);
    uint2 pk;
    pk.x = *(uint32_t*)&h01;
    pk.y = *(uint32_t*)&h23;
    *(uint2*)(Wo + (size_t)o * K + k) = pk;
}

__global__ void k_convert_x(const float4* __restrict__ x, fp16* __restrict__ xo) {
    size_t i = (size_t)blockIdx.x * blockDim.x + threadIdx.x;
    float4 v = x[i];
    __half2* p = (__half2*)(xo + i * 4);
    p[0] = __floats2half2_rn(v.x, v.y);
    p[1] = __floats2half2_rn(v.z, v.w);
}

// ===========================================================================
// GEMM: C[M,N] = A[M,K] * B[N,K]^T + bias, pure fp16, fp32 accum
// CTA tile 128x256, BK=32, 5-stage cp.async pipeline, ONE barrier/iter
// 8 warps = 2(m) x 4(n), warp tile 64x64  (R11 champion config)
// MODE 0: epilogue bias + exact GELU -> fp16 H (row-major)
// MODE 1: epilogue bias -> fp32 out
// ===========================================================================
#define BK 32
#define RSB 80                        // 64B data + 16B pad
#define MAT_A (128 * RSB)             // 10240
#define MAT_Bm (256 * RSB)            // 20480
#define STAGE_B (MAT_A + MAT_Bm)      // 30720
#define NSTAGE 5
#define GSMEM (NSTAGE * STAGE_B)      // 153600

template <int MODE>
__global__ void __launch_bounds__(256, 1)
k_gemm(const fp16* __restrict__ Ax, const fp16* __restrict__ Bw,
       const float* __restrict__ bias, float* __restrict__ outf,
       fp16* __restrict__ outH, int K, int N) {
    extern __shared__ char smem[];
    uint32_t sb = smem_u32(smem);
    int tid = threadIdx.x, wid = tid >> 5, lane = tid & 31;
    int m0 = blockIdx.y * 128;
    int n0 = blockIdx.x * 256;
    int warp_m = (wid >> 2) * 64;
    int warp_n = (wid & 3) * 64;

    int r0i = tid >> 2;               // base row 0..63
    int c0i = tid & 3;                // 16B chunk within 64B row

    float acc[4][8][4];
    #pragma unroll
    for (int i = 0; i < 4; i++)
        #pragma unroll
        for (int j = 0; j < 8; j++)
            #pragma unroll
            for (int q = 0; q < 4; q++) acc[i][j][q] = 0.f;

    int KT = K / BK;

    uint32_t a_off[4], b_off[4];
    #pragma unroll
    for (int mi = 0; mi < 4; mi++)
        a_off[mi] = (uint32_t)((warp_m + mi * 16 + (lane & 15)) * RSB + (lane >> 4) * 16);
    #pragma unroll
    for (int g = 0; g < 4; g++)
        b_off[g] = (uint32_t)(MAT_A + (warp_n + g * 16 + (lane & 15)) * RSB + (lane >> 4) * 16);

    auto load_stage = [&](int slot, int kt) {
        uint32_t st = sb + slot * STAGE_B;
        int kb = kt * BK;
        #pragma unroll
        for (int j = 0; j < 2; j++) {          // A: 128 rows
            int row = r0i + j * 64;
            cp16(st + (uint32_t)(row * RSB + c0i * 16),
                 Ax + (size_t)(m0 + row) * K + kb + c0i * 8);
        }
        #pragma unroll
        for (int j = 0; j < 4; j++) {          // B: 256 rows
            int row = r0i + j * 64;
            cp16(st + (uint32_t)(MAT_A + row * RSB + c0i * 16),
                 Bw + (size_t)(n0 + row) * K + kb + c0i * 8);
        }
        cp_commit();
    };

    load_stage(0, 0);
    load_stage(1, 1);
    load_stage(2, 2);
    load_stage(3, 3);

    for (int kt = 0; kt < KT; kt++) {
        cp_wait3();
        __syncthreads();
        if (kt + 4 < KT) load_stage((kt + 4) % NSTAGE, kt + 4);

        uint32_t st = sb + (kt % NSTAGE) * STAGE_B;
        #pragma unroll
        for (int s = 0; s < 2; s++) {
            uint32_t ks = s * 32;
            uint32_t af[4][4], bf[4][4];
            #pragma unroll
            for (int g = 0; g < 4; g++)
                ldsm4(st + b_off[g] + ks, bf[g][0], bf[g][1], bf[g][2], bf[g][3]);
            #pragma unroll
            for (int mi = 0; mi < 4; mi++)
                ldsm4(st + a_off[mi] + ks, af[mi][0], af[mi][1], af[mi][2], af[mi][3]);
            #pragma unroll
            for (int mi = 0; mi < 4; mi++) {
                #pragma unroll
                for (int ni = 0; ni < 8; ni++) {
                    int g = ni >> 1, sel = ni & 1;
                    mma16816(acc[mi][ni], af[mi], bf[g][sel], bf[g][sel + 2]);
                }
            }
        }
        // no end-of-loop barrier: next iteration's top barrier orders the
        // slot reuse (writes only issued after that barrier).
    }

    // ---- epilogue ----
    int gid = lane >> 2, tig = lane & 3;
    #pragma unroll
    for (int mi = 0; mi < 4; mi++) {
        int row = m0 + warp_m + mi * 16 + gid;
        #pragma unroll
        for (int ni = 0; ni < 8; ni++) {
            int col = n0 + warp_n + ni * 8 + tig * 2;
            float bcol0 = __ldg(&bias[col]), bcol1 = __ldg(&bias[col + 1]);
            #pragma unroll
            for (int half = 0; half < 2; half++) {
                int rr = row + half * 8;
                float v0 = acc[mi][ni][half * 2 + 0] + bcol0;
                float v1 = acc[mi][ni][half * 2 + 1] + bcol1;
                if (MODE == 0) {
                    v0 = 0.5f * v0 * (1.0f + erff(v0 * 0.70710678118654752f));
                    v1 = 0.5f * v1 * (1.0f + erff(v1 * 0.70710678118654752f));
                    *(__half2*)(outH + (size_t)rr * N + col) = __floats2half2_rn(v0, v1);
                } else {
                    float2 v; v.x = v0; v.y = v1;
                    *(float2*)(outf + (size_t)rr * N + col) = v;
                }
            }
        }
    }
}

// ===========================================================================
extern "C" void kernel_launch(void* const* d_in, const int* in_sizes, int n_in,
                              void* d_out, int out_size) {
    const float* x      = (const float*)d_in[0];
    const float* W_fc   = (const float*)d_in[1];
    const float* b_fc   = (const float*)d_in[2];
    const float* A_fc   = (const float*)d_in[3];
    const float* B_fc   = (const float*)d_in[4];
    const float* W_proj = (const float*)d_in[5];
    const float* b_proj = (const float*)d_in[6];
    const float* A_proj = (const float*)d_in[7];
    const float* B_proj = (const float*)d_in[8];
    float* out = (float*)d_out;

    fp16 *x16, *wfc, *h16, *wp;
    cudaGetSymbolAddress((void**)&x16, g_x16);
    cudaGetSymbolAddress((void**)&wfc, g_wfc);
    cudaGetSymbolAddress((void**)&h16, g_h16);
    cudaGetSymbolAddress((void**)&wp,  g_wp);

    cudaFuncSetAttribute(k_gemm<0>, cudaFuncAttributeMaxDynamicSharedMemorySize, GSMEM);
    cudaFuncSetAttribute(k_gemm<1>, cudaFuncAttributeMaxDynamicSharedMemorySize, GSMEM);

    k_init_max<<<1, 32>>>();
    k_absmax2<<<dim3(128, 2), 256>>>(W_fc, W_proj);

    k_quant_w<<<dim3(D / 1024, F), 256>>>(W_fc,   A_fc,   B_fc,   wfc, D, 0);
    k_quant_w<<<dim3(F / 1024, D), 256>>>(W_proj, A_proj, B_proj, wp,  F, 1);
    k_convert_x<<<(MTOT * D / 4) / 256, 256>>>((const float4*)x, x16);

    // GEMM1: [8192,1024] x [4096,1024]^T -> GELU -> fp16 H
    k_gemm<0><<<dim3(F / 256, MTOT / 128), 256, GSMEM>>>(
        x16, wfc, b_fc, nullptr, h16, D, F);
    // GEMM2: [8192,4096] x [1024,4096]^T -> fp32 out
    k_gemm<1><<<dim3(D / 256, MTOT / 128), 256, GSMEM>>>(
        h16, wp, b_proj, out, nullptr, F, D);
}

// round 17
// speedup vs baseline: 1.2422x; 1.0302x over previous
#include <cuda_runtime.h>
#include <cuda_fp16.h>
#include <math.h>
#include <stdint.h>

#define D 1024
#define F 4096
#define MTOT 8192

typedef __half fp16;

// ---- scratch (static device globals: allocation-free) ----
__device__ fp16 g_x16[(size_t)MTOT * D];  // 16 MB
__device__ fp16 g_wfc[(size_t)F * D];     // 8 MB
__device__ fp16 g_h16[(size_t)MTOT * F];  // 64 MB
__device__ fp16 g_wp[(size_t)D * F];      // 8 MB
__device__ unsigned int g_max2[2];

// ===========================================================================
// helpers
// ===========================================================================
__device__ __forceinline__ uint32_t smem_u32(const void* p) {
    uint32_t a;
    asm("{ .reg .u64 t; cvta.to.shared.u64 t, %1; cvt.u32.u64 %0, t; }" : "=r"(a) : "l"(p));
    return a;
}
__device__ __forceinline__ void cp16(uint32_t s, const void* g) {
    asm volatile("cp.async.cg.shared.global [%0], [%1], 16;" :: "r"(s), "l"(g));
}
__device__ __forceinline__ void cp_commit() {
    asm volatile("cp.async.commit_group;");
}
__device__ __forceinline__ void cp_wait3() {
    asm volatile("cp.async.wait_group 3;");
}
__device__ __forceinline__ void ldsm4(uint32_t a, uint32_t& r0, uint32_t& r1,
                                      uint32_t& r2, uint32_t& r3) {
    asm volatile("ldmatrix.sync.aligned.m8n8.x4.shared.b16 {%0,%1,%2,%3}, [%4];"
                 : "=r"(r0), "=r"(r1), "=r"(r2), "=r"(r3) : "r"(a));
}
__device__ __forceinline__ void mma16816(float* c, const uint32_t* a, uint32_t b0, uint32_t b1) {
    asm volatile(
        "mma.sync.aligned.m16n8k16.row.col.f32.f16.f16.f32 "
        "{%0,%1,%2,%3}, {%4,%5,%6,%7}, {%8,%9}, {%0,%1,%2,%3};"
        : "+f"(c[0]), "+f"(c[1]), "+f"(c[2]), "+f"(c[3])
        : "r"(a[0]), "r"(a[1]), "r"(a[2]), "r"(a[3]), "r"(b0), "r"(b1));
}

// ===========================================================================
// pre-pass kernels
// ===========================================================================
__global__ void k_init_max() { g_max2[0] = 0u; g_max2[1] = 0u; }

// blockIdx.y selects tensor (0: W_fc, 1: W_proj); both are F*D floats.
// float4 grid-stride for 4x instruction reduction / MLP.
__global__ void k_absmax2(const float4* __restrict__ W0, const float4* __restrict__ W1) {
    int sel = blockIdx.y;
    const float4* W = sel ? W1 : W0;
    int n4 = (F * D) / 4;
    float m = 0.f;
    int stride = gridDim.x * blockDim.x;
    for (int i = blockIdx.x * blockDim.x + threadIdx.x; i < n4; i += stride) {
        float4 v = W[i];
        m = fmaxf(m, fmaxf(fmaxf(fabsf(v.x), fabsf(v.y)),
                           fmaxf(fabsf(v.z), fabsf(v.w))));
    }
    #pragma unroll
    for (int o = 16; o; o >>= 1) m = fmaxf(m, __shfl_xor_sync(0xffffffffu, m, o));
    __shared__ float sm[8];
    int lane = threadIdx.x & 31, w = threadIdx.x >> 5;
    if (lane == 0) sm[w] = m;
    __syncthreads();
    if (threadIdx.x == 0) {
        float mm = sm[0];
        for (int i = 1; i < 8; i++) mm = fmaxf(mm, sm[i]);
        atomicMax(&g_max2[sel], __float_as_uint(mm));
    }
}

// fakequant(W) + 2*B@A -> single fp16, row-major [out, K]
// 4 output rows per block: A float4 loads amortize across the 4 rows.
// Block covers 1024 cols (256 thr x float4); grid = (K/1024, OUT/4).
__global__ void k_quant_w(const float* __restrict__ W, const float* __restrict__ A,
                          const float* __restrict__ Bm, fp16* __restrict__ Wo,
                          int K, int sel) {
    int o0 = blockIdx.y * 4;
    __shared__ float Bs[4][16];
    if (threadIdx.x < 64)
        Bs[threadIdx.x >> 4][threadIdx.x & 15] = Bm[(o0 + (threadIdx.x >> 4)) * 16 + (threadIdx.x & 15)];
    __syncthreads();
    float mx = __uint_as_float(g_max2[sel]);
    float scale = mx * (1.0f / 127.0f);
    float inv   = 127.0f / mx;
    int k = (blockIdx.x * blockDim.x + threadIdx.x) * 4;

    // LoRA accumulators for 4 rows x 4 cols
    float a_[4][4];
    #pragma unroll
    for (int r4 = 0; r4 < 4; r4++)
        #pragma unroll
        for (int q = 0; q < 4; q++) a_[r4][q] = 0.f;
    #pragma unroll
    for (int r = 0; r < 16; r++) {
        float4 av = *(const float4*)(A + (size_t)r * K + k);
        #pragma unroll
        for (int r4 = 0; r4 < 4; r4++) {
            float b = Bs[r4][r];
            a_[r4][0] = fmaf(b, av.x, a_[r4][0]);
            a_[r4][1] = fmaf(b, av.y, a_[r4][1]);
            a_[r4][2] = fmaf(b, av.z, a_[r4][2]);
            a_[r4][3] = fmaf(b, av.w, a_[r4][3]);
        }
    }
    #pragma unroll
    for (int r4 = 0; r4 < 4; r4++) {
        int o = o0 + r4;
        float4 w4 = *(const float4*)(W + (size_t)o * K + k);
        float q0 = fminf(fmaxf(rintf(w4.x * inv), -128.f), 127.f) * scale;
        float q1 = fminf(fmaxf(rintf(w4.y * inv), -128.f), 127.f) * scale;
        float q2 = fminf(fmaxf(rintf(w4.z * inv), -128.f), 127.f) * scale;
        float q3 = fminf(fmaxf(rintf(w4.w * inv), -128.f), 127.f) * scale;
        __half2 h01 = __floats2half2_rn(q0 + 2.0f * a_[r4][0], q1 + 2.0f * a_[r4][1]);
        __half2 h23 = __floats2half2_rn(q2 + 2.0f * a_[r4][2], q3 + 2.0f * a_[r4][3]);
        uint2 pk;
        pk.x = *(uint32_t*)&h01;
        pk.y = *(uint32_t*)&h23;
        *(uint2*)(Wo + (size_t)o * K + k) = pk;
    }
}

__global__ void k_convert_x(const float4* __restrict__ x, fp16* __restrict__ xo) {
    size_t i = (size_t)blockIdx.x * blockDim.x + threadIdx.x;
    float4 v = x[i];
    __half2* p = (__half2*)(xo + i * 4);
    p[0] = __floats2half2_rn(v.x, v.y);
    p[1] = __floats2half2_rn(v.z, v.w);
}

// ===========================================================================
// GEMM: C[M,N] = A[M,K] * B[N,K]^T + bias, pure fp16, fp32 accum
// CTA tile 128x256, BK=32, 5-stage cp.async pipeline, ONE barrier/iter
// 8 warps = 2(m) x 4(n), warp tile 64x64  (R11/R15 champion config)
// MODE 0: epilogue bias + exact GELU -> fp16 H (row-major)
// MODE 1: epilogue bias -> fp32 out
// ===========================================================================
#define BK 32
#define RSB 80                        // 64B data + 16B pad
#define MAT_A (128 * RSB)             // 10240
#define MAT_Bm (256 * RSB)            // 20480
#define STAGE_B (MAT_A + MAT_Bm)      // 30720
#define NSTAGE 5
#define GSMEM (NSTAGE * STAGE_B)      // 153600

template <int MODE>
__global__ void __launch_bounds__(256, 1)
k_gemm(const fp16* __restrict__ Ax, const fp16* __restrict__ Bw,
       const float* __restrict__ bias, float* __restrict__ outf,
       fp16* __restrict__ outH, int K, int N) {
    extern __shared__ char smem[];
    uint32_t sb = smem_u32(smem);
    int tid = threadIdx.x, wid = tid >> 5, lane = tid & 31;
    int m0 = blockIdx.y * 128;
    int n0 = blockIdx.x * 256;
    int warp_m = (wid >> 2) * 64;
    int warp_n = (wid & 3) * 64;

    int r0i = tid >> 2;               // base row 0..63
    int c0i = tid & 3;                // 16B chunk within 64B row

    float acc[4][8][4];
    #pragma unroll
    for (int i = 0; i < 4; i++)
        #pragma unroll
        for (int j = 0; j < 8; j++)
            #pragma unroll
            for (int q = 0; q < 4; q++) acc[i][j][q] = 0.f;

    int KT = K / BK;

    uint32_t a_off[4], b_off[4];
    #pragma unroll
    for (int mi = 0; mi < 4; mi++)
        a_off[mi] = (uint32_t)((warp_m + mi * 16 + (lane & 15)) * RSB + (lane >> 4) * 16);
    #pragma unroll
    for (int g = 0; g < 4; g++)
        b_off[g] = (uint32_t)(MAT_A + (warp_n + g * 16 + (lane & 15)) * RSB + (lane >> 4) * 16);

    auto load_stage = [&](int slot, int kt) {
        uint32_t st = sb + slot * STAGE_B;
        int kb = kt * BK;
        #pragma unroll
        for (int j = 0; j < 2; j++) {          // A: 128 rows
            int row = r0i + j * 64;
            cp16(st + (uint32_t)(row * RSB + c0i * 16),
                 Ax + (size_t)(m0 + row) * K + kb + c0i * 8);
        }
        #pragma unroll
        for (int j = 0; j < 4; j++) {          // B: 256 rows
            int row = r0i + j * 64;
            cp16(st + (uint32_t)(MAT_A + row * RSB + c0i * 16),
                 Bw + (size_t)(n0 + row) * K + kb + c0i * 8);
        }
        cp_commit();
    };

    load_stage(0, 0);
    load_stage(1, 1);
    load_stage(2, 2);
    load_stage(3, 3);

    for (int kt = 0; kt < KT; kt++) {
        cp_wait3();
        __syncthreads();
        if (kt + 4 < KT) load_stage((kt + 4) % NSTAGE, kt + 4);

        uint32_t st = sb + (kt % NSTAGE) * STAGE_B;
        #pragma unroll
        for (int s = 0; s < 2; s++) {
            uint32_t ks = s * 32;
            uint32_t af[4][4], bf[4][4];
            #pragma unroll
            for (int g = 0; g < 4; g++)
                ldsm4(st + b_off[g] + ks, bf[g][0], bf[g][1], bf[g][2], bf[g][3]);
            #pragma unroll
            for (int mi = 0; mi < 4; mi++)
                ldsm4(st + a_off[mi] + ks, af[mi][0], af[mi][1], af[mi][2], af[mi][3]);
            #pragma unroll
            for (int mi = 0; mi < 4; mi++) {
                #pragma unroll
                for (int ni = 0; ni < 8; ni++) {
                    int g = ni >> 1, sel = ni & 1;
                    mma16816(acc[mi][ni], af[mi], bf[g][sel], bf[g][sel + 2]);
                }
            }
        }
        // no end-of-loop barrier: next iteration's top barrier orders the
        // slot reuse (writes only issued after that barrier).
    }

    // ---- epilogue ----
    int gid = lane >> 2, tig = lane & 3;
    #pragma unroll
    for (int mi = 0; mi < 4; mi++) {
        int row = m0 + warp_m + mi * 16 + gid;
        #pragma unroll
        for (int ni = 0; ni < 8; ni++) {
            int col = n0 + warp_n + ni * 8 + tig * 2;
            float bcol0 = __ldg(&bias[col]), bcol1 = __ldg(&bias[col + 1]);
            #pragma unroll
            for (int half = 0; half < 2; half++) {
                int rr = row + half * 8;
                float v0 = acc[mi][ni][half * 2 + 0] + bcol0;
                float v1 = acc[mi][ni][half * 2 + 1] + bcol1;
                if (MODE == 0) {
                    v0 = 0.5f * v0 * (1.0f + erff(v0 * 0.70710678118654752f));
                    v1 = 0.5f * v1 * (1.0f + erff(v1 * 0.70710678118654752f));
                    *(__half2*)(outH + (size_t)rr * N + col) = __floats2half2_rn(v0, v1);
                } else {
                    float2 v; v.x = v0; v.y = v1;
                    *(float2*)(outf + (size_t)rr * N + col) = v;
                }
            }
        }
    }
}

// ===========================================================================
extern "C" void kernel_launch(void* const* d_in, const int* in_sizes, int n_in,
                              void* d_out, int out_size) {
    const float* x      = (const float*)d_in[0];
    const float* W_fc   = (const float*)d_in[1];
    const float* b_fc   = (const float*)d_in[2];
    const float* A_fc   = (const float*)d_in[3];
    const float* B_fc   = (const float*)d_in[4];
    const float* W_proj = (const float*)d_in[5];
    const float* b_proj = (const float*)d_in[6];
    const float* A_proj = (const float*)d_in[7];
    const float* B_proj = (const float*)d_in[8];
    float* out = (float*)d_out;

    fp16 *x16, *wfc, *h16, *wp;
    cudaGetSymbolAddress((void**)&x16, g_x16);
    cudaGetSymbolAddress((void**)&wfc, g_wfc);
    cudaGetSymbolAddress((void**)&h16, g_h16);
    cudaGetSymbolAddress((void**)&wp,  g_wp);

    cudaFuncSetAttribute(k_gemm<0>, cudaFuncAttributeMaxDynamicSharedMemorySize, GSMEM);
    cudaFuncSetAttribute(k_gemm<1>, cudaFuncAttributeMaxDynamicSharedMemorySize, GSMEM);

    k_init_max<<<1, 32>>>();
    k_absmax2<<<dim3(256, 2), 256>>>((const float4*)W_fc, (const float4*)W_proj);

    k_quant_w<<<dim3(D / 1024, F / 4), 256>>>(W_fc,   A_fc,   B_fc,   wfc, D, 0);
    k_quant_w<<<dim3(F / 1024, D / 4), 256>>>(W_proj, A_proj, B_proj, wp,  F, 1);
    k_convert_x<<<(MTOT * D / 4) / 256, 256>>>((const float4*)x, x16);

    // GEMM1: [8192,1024] x [4096,1024]^T -> GELU -> fp16 H
    k_gemm<0><<<dim3(F / 256, MTOT / 128), 256, GSMEM>>>(
        x16, wfc, b_fc, nullptr, h16, D, F);
    // GEMM2: [8192,4096] x [1024,4096]^T -> fp32 out
    k_gemm<1><<<dim3(D / 256, MTOT / 128), 256, GSMEM>>>(
        h16, wp, b_proj, out, nullptr, F, D);
}